// round 1
// baseline (speedup 1.0000x reference)
#include <cuda_runtime.h>
#include <cstddef>

#define N_NODES 100000
#define N_EDGES 1600000
#define HIDC    128
#define N_TRUCK 32

// ---------------- device scratch (allocation-free rule: static globals) -----
__device__ float g_bufA[(size_t)N_NODES * HIDC];
__device__ float g_bufB[(size_t)N_NODES * HIDC];
__device__ float g_agg [(size_t)N_NODES * HIDC];
__device__ int   g_cnt[N_NODES];
__device__ int   g_cursor[N_NODES];
__device__ int   g_rowptr[N_NODES + 1];
__device__ int   g_srcsorted[N_EDGES];
__device__ int   g_blocksums[128];

// ---------------- CSR build ------------------------------------------------
__global__ void zero_cnt_kernel() {
    int i = blockIdx.x * blockDim.x + threadIdx.x;
    if (i < N_NODES) g_cnt[i] = 0;
}

__global__ void hist_kernel(const int* __restrict__ dst) {
    int i = blockIdx.x * blockDim.x + threadIdx.x;
    if (i < N_EDGES) atomicAdd(&g_cnt[dst[i]], 1);
}

// inclusive scan per 1024-block
__global__ void scan_phase1() {
    __shared__ int sh[1024];
    int i = blockIdx.x * 1024 + threadIdx.x;
    int v = (i < N_NODES) ? g_cnt[i] : 0;
    sh[threadIdx.x] = v;
    __syncthreads();
    for (int off = 1; off < 1024; off <<= 1) {
        int t = (threadIdx.x >= off) ? sh[threadIdx.x - off] : 0;
        __syncthreads();
        sh[threadIdx.x] += t;
        __syncthreads();
    }
    if (i < N_NODES) g_rowptr[i] = sh[threadIdx.x];
    if (threadIdx.x == 1023) g_blocksums[blockIdx.x] = sh[1023];
}

__global__ void scan_phase2(int nb) {
    if (threadIdx.x == 0 && blockIdx.x == 0) {
        int acc = 0;
        for (int b = 0; b < nb; ++b) {
            int t = g_blocksums[b];
            g_blocksums[b] = acc;
            acc += t;
        }
    }
}

__global__ void scan_phase3() {
    int i = blockIdx.x * blockDim.x + threadIdx.x;
    if (i < N_NODES) {
        int excl = g_rowptr[i] - g_cnt[i] + g_blocksums[i >> 10];
        g_rowptr[i] = excl;
        g_cursor[i] = excl;
    }
    if (i == 0) g_rowptr[N_NODES] = N_EDGES;
}

__global__ void fill_kernel(const int* __restrict__ src, const int* __restrict__ dst) {
    int i = blockIdx.x * blockDim.x + threadIdx.x;
    if (i < N_EDGES) {
        int p = atomicAdd(&g_cursor[dst[i]], 1);
        g_srcsorted[p] = src[i];
    }
}

// ---------------- aggregation: one warp per dst node, float4 per lane ------
__global__ void __launch_bounds__(256) agg_kernel(const float* __restrict__ h,
                                                  float* __restrict__ agg) {
    int gw   = (blockIdx.x * blockDim.x + threadIdx.x) >> 5;
    int lane = threadIdx.x & 31;
    if (gw >= N_NODES) return;
    int beg = g_rowptr[gw];
    int end = g_rowptr[gw + 1];
    float ax = 0.f, ay = 0.f, az = 0.f, aw = 0.f;
    int e = beg;
    int s_next = (e < end) ? g_srcsorted[e] : 0;
    for (; e < end; ++e) {
        int s = s_next;
        if (e + 1 < end) s_next = g_srcsorted[e + 1];
        float4 v = __ldg((const float4*)(h + (size_t)s * HIDC + lane * 4));
        ax += v.x; ay += v.y; az += v.z; aw += v.w;
    }
    float4 o = make_float4(ax, ay, az, aw);
    *(float4*)(agg + (size_t)gw * HIDC + lane * 4) = o;
}

// ---------------- fused dual-A GEMM: out = act(A1@W1 + A2@W2 + bias) -------
// BM=128, BN=128, BK=16, 256 threads, per-thread 8x8 split as 2x2 float4 tiles
template <bool RELU>
__global__ void __launch_bounds__(256) gemm_kernel(
    const float* __restrict__ A1, const float* __restrict__ W1,
    const float* __restrict__ A2, const float* __restrict__ W2,
    const float* __restrict__ bias, float* __restrict__ out)
{
    __shared__ float As[16][128];   // As[k][m]
    __shared__ float Ws[16][128];   // Ws[k][n]
    const int tid = threadIdx.x;
    const int tx = tid & 15;        // N direction
    const int ty = tid >> 4;        // M direction
    const int block_row = blockIdx.x * 128;
    const int c0 = tx * 4;
    const int r0 = ty * 4;

    float acc[2][2][4][4];
#pragma unroll
    for (int a = 0; a < 2; ++a)
#pragma unroll
        for (int b = 0; b < 2; ++b)
#pragma unroll
            for (int i = 0; i < 4; ++i)
#pragma unroll
                for (int j = 0; j < 4; ++j) acc[a][b][i][j] = 0.f;

    const int kt_beg = (A1 == nullptr) ? 8 : 0;
    for (int kt = kt_beg; kt < 16; ++kt) {
        const float* Ap = (kt < 8) ? A1 : A2;
        const float* Wp = (kt < 8) ? W1 : W2;
        const int k0 = (kt & 7) * 16;
        // A tile: 128 rows x 16 cols, stored transposed
#pragma unroll
        for (int r = 0; r < 2; ++r) {
            int idx = tid + r * 256;      // 0..511 float4 slots
            int row = idx >> 2;           // 0..127
            int cc  = (idx & 3) * 4;      // 0,4,8,12
            int grow = block_row + row;
            float4 v = make_float4(0.f, 0.f, 0.f, 0.f);
            if (grow < N_NODES)
                v = __ldg((const float4*)(Ap + (size_t)grow * 128 + k0 + cc));
            As[cc + 0][row] = v.x;
            As[cc + 1][row] = v.y;
            As[cc + 2][row] = v.z;
            As[cc + 3][row] = v.w;
        }
        // W tile: 16 rows (k) x 128 cols
#pragma unroll
        for (int r = 0; r < 2; ++r) {
            int idx  = tid + r * 256;     // 0..511
            int krow = idx >> 5;          // 0..15
            int cc   = (idx & 31) * 4;
            *(float4*)&Ws[krow][cc] =
                __ldg((const float4*)(Wp + (size_t)(k0 + krow) * 128 + cc));
        }
        __syncthreads();
#pragma unroll
        for (int k = 0; k < 16; ++k) {
            float4 a0 = *(const float4*)&As[k][r0];
            float4 a1 = *(const float4*)&As[k][r0 + 64];
            float4 b0 = *(const float4*)&Ws[k][c0];
            float4 b1 = *(const float4*)&Ws[k][c0 + 64];
            float av[2][4] = {{a0.x, a0.y, a0.z, a0.w}, {a1.x, a1.y, a1.z, a1.w}};
            float bv[2][4] = {{b0.x, b0.y, b0.z, b0.w}, {b1.x, b1.y, b1.z, b1.w}};
#pragma unroll
            for (int a = 0; a < 2; ++a)
#pragma unroll
                for (int i = 0; i < 4; ++i)
#pragma unroll
                    for (int b = 0; b < 2; ++b)
#pragma unroll
                        for (int j = 0; j < 4; ++j)
                            acc[a][b][i][j] += av[a][i] * bv[b][j];
        }
        __syncthreads();
    }

    float4 bias0 = __ldg((const float4*)(bias + c0));
    float4 bias1 = __ldg((const float4*)(bias + c0 + 64));
    float bb[2][4] = {{bias0.x, bias0.y, bias0.z, bias0.w},
                      {bias1.x, bias1.y, bias1.z, bias1.w}};
#pragma unroll
    for (int a = 0; a < 2; ++a) {
#pragma unroll
        for (int i = 0; i < 4; ++i) {
            int row = block_row + a * 64 + r0 + i;
            if (row < N_NODES) {
#pragma unroll
                for (int b = 0; b < 2; ++b) {
                    float4 v;
                    v.x = acc[a][b][i][0] + bb[b][0];
                    v.y = acc[a][b][i][1] + bb[b][1];
                    v.z = acc[a][b][i][2] + bb[b][2];
                    v.w = acc[a][b][i][3] + bb[b][3];
                    if (RELU) {
                        v.x = fmaxf(v.x, 0.f); v.y = fmaxf(v.y, 0.f);
                        v.z = fmaxf(v.z, 0.f); v.w = fmaxf(v.w, 0.f);
                    }
                    *(float4*)(out + (size_t)row * 128 + b * 64 + c0) = v;
                }
            }
        }
    }
}

// ---------------- head: logits = t @ Wc1 + bc1  (N=32) ---------------------
__global__ void __launch_bounds__(256) head2_kernel(
    const float* __restrict__ t, const float* __restrict__ Wc1,
    const float* __restrict__ bc1, float* __restrict__ out)
{
    __shared__ float Ws[HIDC * N_TRUCK];   // 16 KB
    __shared__ float bs[N_TRUCK];
    int tid = threadIdx.x;
#pragma unroll
    for (int r = 0; r < 4; ++r) {
        int idx = tid + r * 256;           // 0..1023 float4 slots over 4096 floats
        *(float4*)&Ws[idx * 4] = __ldg((const float4*)(Wc1 + idx * 4));
    }
    if (tid < N_TRUCK) bs[tid] = bc1[tid];
    __syncthreads();

    int row = blockIdx.x * 8 + (tid >> 5);
    int col = tid & 31;
    if (row >= N_NODES) return;
    const float* trow = t + (size_t)row * HIDC;
    float acc = bs[col];
#pragma unroll
    for (int k4 = 0; k4 < 32; ++k4) {
        float4 v = __ldg((const float4*)(trow + k4 * 4));
        acc += v.x * Ws[(k4 * 4 + 0) * N_TRUCK + col];
        acc += v.y * Ws[(k4 * 4 + 1) * N_TRUCK + col];
        acc += v.z * Ws[(k4 * 4 + 2) * N_TRUCK + col];
        acc += v.w * Ws[(k4 * 4 + 3) * N_TRUCK + col];
    }
    out[(size_t)row * N_TRUCK + col] = acc;
}

// ---------------- launch ----------------------------------------------------
extern "C" void kernel_launch(void* const* d_in, const int* in_sizes, int n_in,
                              void* d_out, int out_size)
{
    const float* x      = (const float*)d_in[0];
    const int*   ei     = (const int*)d_in[1];
    const float* W_rel0 = (const float*)d_in[2];
    const float* b_rel0 = (const float*)d_in[3];
    const float* W_root0= (const float*)d_in[4];
    const float* W_rel1 = (const float*)d_in[5];
    const float* b_rel1 = (const float*)d_in[6];
    const float* W_root1= (const float*)d_in[7];
    const float* W_rel2 = (const float*)d_in[8];
    const float* b_rel2 = (const float*)d_in[9];
    const float* W_root2= (const float*)d_in[10];
    const float* Wc0    = (const float*)d_in[11];
    const float* bc0    = (const float*)d_in[12];
    const float* Wc1    = (const float*)d_in[13];
    const float* bc1    = (const float*)d_in[14];
    float* out = (float*)d_out;

    const int* srcp = ei;
    const int* dstp = ei + N_EDGES;

    float *bufA, *bufB, *agg;
    cudaGetSymbolAddress((void**)&bufA, g_bufA);
    cudaGetSymbolAddress((void**)&bufB, g_bufB);
    cudaGetSymbolAddress((void**)&agg,  g_agg);

    const int nbScan = (N_NODES + 1023) / 1024;          // 98

    // CSR build (dst-sorted)
    zero_cnt_kernel<<<(N_NODES + 255) / 256, 256>>>();
    hist_kernel<<<(N_EDGES + 255) / 256, 256>>>(dstp);
    scan_phase1<<<nbScan, 1024>>>();
    scan_phase2<<<1, 32>>>(nbScan);
    scan_phase3<<<(N_NODES + 255) / 256, 256>>>();
    fill_kernel<<<(N_EDGES + 255) / 256, 256>>>(srcp, dstp);

    const int aggGrid  = (N_NODES * 32 + 255) / 256;     // 12500
    const int gemmGrid = (N_NODES + 127) / 128;          // 782

    // layer 0: x -> bufA
    agg_kernel<<<aggGrid, 256>>>(x, agg);
    gemm_kernel<true><<<gemmGrid, 256>>>(agg, W_rel0, x, W_root0, b_rel0, bufA);
    // layer 1: bufA -> bufB
    agg_kernel<<<aggGrid, 256>>>(bufA, agg);
    gemm_kernel<true><<<gemmGrid, 256>>>(agg, W_rel1, bufA, W_root1, b_rel1, bufB);
    // layer 2: bufB -> bufA
    agg_kernel<<<aggGrid, 256>>>(bufB, agg);
    gemm_kernel<true><<<gemmGrid, 256>>>(agg, W_rel2, bufB, W_root2, b_rel2, bufA);
    // head linear 1: bufA -> bufB (relu)
    gemm_kernel<true><<<gemmGrid, 256>>>(nullptr, nullptr, bufA, Wc0, bc0, bufB);
    // head linear 2: bufB -> logits
    head2_kernel<<<(N_NODES + 7) / 8, 256>>>(bufB, Wc1, bc1, out);
    (void)in_sizes; (void)n_in; (void)out_size;
}

// round 4
// speedup vs baseline: 1.4469x; 1.4469x over previous
#include <cuda_runtime.h>
#include <cuda_bf16.h>
#include <cstdint>
#include <cstddef>

#define N_NODES 100000
#define N_EDGES 1600000
#define HIDC    128
#define N_TRUCK 32

// ---------------- device scratch ------------------------------------------
__device__ float         g_F   [(size_t)N_NODES * HIDC];     // full-precision h
__device__ __nv_bfloat16 g_p0h [(size_t)N_NODES * HIDC];
__device__ __nv_bfloat16 g_p0l [(size_t)N_NODES * HIDC];
__device__ __nv_bfloat16 g_p1h [(size_t)N_NODES * HIDC];
__device__ __nv_bfloat16 g_p1l [(size_t)N_NODES * HIDC];
__device__ __nv_bfloat16 g_agh [(size_t)N_NODES * HIDC];
__device__ __nv_bfloat16 g_agl [(size_t)N_NODES * HIDC];
__device__ __nv_bfloat16 g_wtb [14 * 16384];                 // transposed split weights
__device__ int   g_cnt[N_NODES];
__device__ int   g_cursor[N_NODES];
__device__ int   g_rowptr[N_NODES + 1];
__device__ int   g_srcsorted[N_EDGES];
__device__ int   g_blocksums[128];

// ---------------- helpers ---------------------------------------------------
__device__ __forceinline__ uint32_t smem_u32(const void* p) {
    uint32_t a;
    asm("{ .reg .u64 t; cvta.to.shared.u64 t, %1; cvt.u32.u64 %0, t; }" : "=r"(a) : "l"(p));
    return a;
}

__device__ __forceinline__ void split2(float a, float b, uint32_t& h, uint32_t& l) {
    __nv_bfloat162 hh = __floats2bfloat162_rn(a, b);
    __nv_bfloat162 ll = __floats2bfloat162_rn(a - __bfloat162float(hh.x),
                                              b - __bfloat162float(hh.y));
    h = *reinterpret_cast<uint32_t*>(&hh);
    l = *reinterpret_cast<uint32_t*>(&ll);
}
__device__ __forceinline__ void split4(float a, float b, float c, float d,
                                       uint32_t& h01, uint32_t& h23,
                                       uint32_t& l01, uint32_t& l23) {
    split2(a, b, h01, l01);
    split2(c, d, h23, l23);
}

__device__ __forceinline__ void ldm_x4(uint32_t& r0, uint32_t& r1, uint32_t& r2,
                                       uint32_t& r3, uint32_t addr) {
    asm volatile("ldmatrix.sync.aligned.m8n8.x4.shared.b16 {%0,%1,%2,%3}, [%4];"
                 : "=r"(r0), "=r"(r1), "=r"(r2), "=r"(r3) : "r"(addr));
}
__device__ __forceinline__ void mma16816(float* c, const uint32_t* a, const uint32_t* b) {
    asm volatile("mma.sync.aligned.m16n8k16.row.col.f32.bf16.bf16.f32 "
                 "{%0,%1,%2,%3}, {%4,%5,%6,%7}, {%8,%9}, {%0,%1,%2,%3};"
                 : "+f"(c[0]), "+f"(c[1]), "+f"(c[2]), "+f"(c[3])
                 : "r"(a[0]), "r"(a[1]), "r"(a[2]), "r"(a[3]), "r"(b[0]), "r"(b[1]));
}

// ---------------- CSR build ------------------------------------------------
__global__ void zero_cnt_kernel() {
    int i = blockIdx.x * blockDim.x + threadIdx.x;
    if (i < N_NODES) g_cnt[i] = 0;
}
__global__ void hist_kernel(const int* __restrict__ dst) {
    int i = blockIdx.x * blockDim.x + threadIdx.x;
    if (i < N_EDGES) atomicAdd(&g_cnt[dst[i]], 1);
}
__global__ void scan_phase1() {
    __shared__ int sh[1024];
    int i = blockIdx.x * 1024 + threadIdx.x;
    int v = (i < N_NODES) ? g_cnt[i] : 0;
    sh[threadIdx.x] = v;
    __syncthreads();
    for (int off = 1; off < 1024; off <<= 1) {
        int t = (threadIdx.x >= off) ? sh[threadIdx.x - off] : 0;
        __syncthreads();
        sh[threadIdx.x] += t;
        __syncthreads();
    }
    if (i < N_NODES) g_rowptr[i] = sh[threadIdx.x];
    if (threadIdx.x == 1023) g_blocksums[blockIdx.x] = sh[1023];
}
__global__ void scan_phase2(int nb) {
    if (threadIdx.x == 0 && blockIdx.x == 0) {
        int acc = 0;
        for (int b = 0; b < nb; ++b) { int t = g_blocksums[b]; g_blocksums[b] = acc; acc += t; }
    }
}
__global__ void scan_phase3() {
    int i = blockIdx.x * blockDim.x + threadIdx.x;
    if (i < N_NODES) {
        int excl = g_rowptr[i] - g_cnt[i] + g_blocksums[i >> 10];
        g_rowptr[i] = excl;
        g_cursor[i] = excl;
    }
    if (i == 0) g_rowptr[N_NODES] = N_EDGES;
}
__global__ void fill_kernel(const int* __restrict__ src, const int* __restrict__ dst) {
    int i = blockIdx.x * blockDim.x + threadIdx.x;
    if (i < N_EDGES) {
        int p = atomicAdd(&g_cursor[dst[i]], 1);
        g_srcsorted[p] = src[i];
    }
}

// ---------------- split x -> bf16 hi/lo ------------------------------------
__global__ void split_kernel(const float* __restrict__ src,
                             __nv_bfloat16* __restrict__ hi,
                             __nv_bfloat16* __restrict__ lo, int n4) {
    int i = blockIdx.x * blockDim.x + threadIdx.x;
    if (i >= n4) return;
    float4 v = __ldg((const float4*)src + i);
    uint32_t h01, h23, l01, l23;
    split4(v.x, v.y, v.z, v.w, h01, h23, l01, l23);
    *(uint2*)(hi + (size_t)i * 4) = make_uint2(h01, h23);
    *(uint2*)(lo + (size_t)i * 4) = make_uint2(l01, l23);
}

// ---------------- weight prep: transpose + split ----------------------------
__global__ void wprep_kernel(const float* __restrict__ w0, const float* __restrict__ w1,
                             const float* __restrict__ w2, const float* __restrict__ w3,
                             const float* __restrict__ w4, const float* __restrict__ w5,
                             const float* __restrict__ w6) {
    int gid = blockIdx.x * blockDim.x + threadIdx.x;
    if (gid >= 7 * 16384) return;
    int m = gid >> 14;
    int r = gid & 16383;
    int n = r >> 7;
    int k = r & 127;
    const float* W = (m == 0) ? w0 : (m == 1) ? w1 : (m == 2) ? w2 : (m == 3) ? w3
                   : (m == 4) ? w4 : (m == 5) ? w5 : w6;
    float v = __ldg(W + k * 128 + n);
    __nv_bfloat16 h = __float2bfloat16(v);
    __nv_bfloat16 l = __float2bfloat16(v - __bfloat162float(h));
    int hidx = (m < 6) ? ((m >> 1) * 4 + (m & 1) * 2) : 12;
    g_wtb[(size_t)hidx * 16384 + n * 128 + k] = h;
    g_wtb[(size_t)(hidx + 1) * 16384 + n * 128 + k] = l;
}

// ---------------- aggregation: warp per node, writes bf16 hi/lo pair -------
__global__ void __launch_bounds__(256) agg_kernel(const float* __restrict__ h,
                                                  __nv_bfloat16* __restrict__ ahi,
                                                  __nv_bfloat16* __restrict__ alo) {
    int gw   = (blockIdx.x * blockDim.x + threadIdx.x) >> 5;
    int lane = threadIdx.x & 31;
    if (gw >= N_NODES) return;
    int beg = g_rowptr[gw];
    int end = g_rowptr[gw + 1];
    float ax = 0.f, ay = 0.f, az = 0.f, aw = 0.f;
    int e = beg;
    int s_next = (e < end) ? g_srcsorted[e] : 0;
    for (; e < end; ++e) {
        int s = s_next;
        if (e + 1 < end) s_next = g_srcsorted[e + 1];
        float4 v = __ldg((const float4*)(h + (size_t)s * HIDC + lane * 4));
        ax += v.x; ay += v.y; az += v.z; aw += v.w;
    }
    uint32_t h01, h23, l01, l23;
    split4(ax, ay, az, aw, h01, h23, l01, l23);
    size_t off = (size_t)gw * HIDC + lane * 4;
    *(uint2*)(ahi + off) = make_uint2(h01, h23);
    *(uint2*)(alo + off) = make_uint2(l01, l23);
}

// ---------------- mma.sync bf16x3 GEMM --------------------------------------
// out = act( [A1|A2] @ [B1;B2] + bias ), operands pre-split hi/lo bf16,
// B given transposed Bt[n][k]. Products: ah*bh + ah*bl + al*bh (fp32 acc).
// CTA tile 128x128, 8 warps (2m x 4n), warp tile 64x32, K-chunks of 64.
#define KC       64
#define PITCH    144                       // (64+8) halves * 2B, conflict-free ldmatrix
#define TILE_B   (128 * PITCH)             // 18432 B
#define STAGE_B  (4 * TILE_B)              // Ahi, Alo, Bhi, Blo = 73728 B
#define GEMM_SMEM (2 * STAGE_B)            // 147456 B

__global__ void __launch_bounds__(256, 1) gemm_mma(
    const __nv_bfloat16* __restrict__ a1h, const __nv_bfloat16* __restrict__ a1l,
    const __nv_bfloat16* __restrict__ a2h, const __nv_bfloat16* __restrict__ a2l,
    const __nv_bfloat16* __restrict__ b1h, const __nv_bfloat16* __restrict__ b1l,
    const __nv_bfloat16* __restrict__ b2h, const __nv_bfloat16* __restrict__ b2l,
    const float* __restrict__ bias,
    float* __restrict__ outf,
    __nv_bfloat16* __restrict__ outhi, __nv_bfloat16* __restrict__ outlo,
    int nc, int k1c)
{
    extern __shared__ char smem[];
    const uint32_t sbase = smem_u32(smem);
    const int tid  = threadIdx.x;
    const int wid  = tid >> 5;
    const int lane = tid & 31;
    const int wm = wid >> 2;            // 0..1  (64-row slab)
    const int wn = wid & 3;             // 0..3  (32-col slab)
    const int block_row = blockIdx.x * 128;

    float acc[4][4][4];
#pragma unroll
    for (int i = 0; i < 4; ++i)
#pragma unroll
        for (int j = 0; j < 4; ++j)
#pragma unroll
            for (int k = 0; k < 4; ++k) acc[i][j][k] = 0.f;

    // ---- chunk source selection ----
    auto pick = [&](int kc, const __nv_bfloat16*& ah, const __nv_bfloat16*& al,
                    const __nv_bfloat16*& bh, const __nv_bfloat16*& bl, int& acol) {
        if (kc < k1c) { ah = a1h; al = a1l; bh = b1h; bl = b1l; acol = kc * KC; }
        else          { ah = a2h; al = a2l; bh = b2h; bl = b2l; acol = (kc - k1c) * KC; }
    };

    // ---- global->smem for one batch (8 of 16 chunk-slots) ----
    // slot t (0..15): buf = t>>2 (0:Ahi 1:Alo 2:Bhi 3:Blo), w = tid + (t&3)*256,
    // row = w>>3 (0..127), q = w&7 (16B column chunk)
    auto ldg_batch = [&](int kc, int tbeg, uint4* regs) {
        const __nv_bfloat16 *ah, *al, *bh, *bl; int acol;
        pick(kc, ah, al, bh, bl, acol);
#pragma unroll
        for (int t = 0; t < 8; ++t) {
            const int slot = tbeg + t;
            const int buf = slot >> 2;
            const int w = tid + (slot & 3) * 256;
            const int row = w >> 3;
            const int q = w & 7;
            uint4 v = make_uint4(0, 0, 0, 0);
            if (buf < 2) {
                int grow = block_row + row;
                if (grow < N_NODES) {
                    const __nv_bfloat16* src = (buf == 0) ? ah : al;
                    v = *(const uint4*)(src + (size_t)grow * 128 + acol + q * 8);
                }
            } else {
                const __nv_bfloat16* src = (buf == 2) ? bh : bl;
                v = *(const uint4*)(src + (size_t)row * 128 + acol + q * 8);
            }
            regs[t] = v;
        }
    };
    auto sts_batch = [&](int stage, int tbeg, const uint4* regs) {
        const uint32_t so = sbase + stage * STAGE_B;
#pragma unroll
        for (int t = 0; t < 8; ++t) {
            const int slot = tbeg + t;
            const int buf = slot >> 2;
            const int w = tid + (slot & 3) * 256;
            const int row = w >> 3;
            const int q = w & 7;
            *(uint4*)(smem + (so - sbase) + buf * TILE_B + row * PITCH + q * 16) = regs[t];
        }
    };

    // ---- compute two k16-steps from current stage ----
    const int r8  = lane & 7;
    const int sub = lane >> 3;
    auto compute2 = [&](int stage, int ks0) {
        const uint32_t so = sbase + stage * STAGE_B;
        const uint32_t Ah = so;
        const uint32_t Al = so + TILE_B;
        const uint32_t Bh = so + 2 * TILE_B;
        const uint32_t Bl = so + 3 * TILE_B;
#pragma unroll
        for (int ks = ks0; ks < ks0 + 2; ++ks) {
            uint32_t ah[4][4], al[4][4], bh[4][2], bl[4][2];
            // A frags: lane mapping sub0: r, sub1: r+8, sub2: r(+16B), sub3: r+8(+16B)
#pragma unroll
            for (int mi = 0; mi < 4; ++mi) {
                const int arow = wm * 64 + mi * 16 + r8 + (sub & 1) * 8;
                const uint32_t addr = arow * PITCH + ks * 32 + (sub >> 1) * 16;
                ldm_x4(ah[mi][0], ah[mi][1], ah[mi][2], ah[mi][3], Ah + addr);
                ldm_x4(al[mi][0], al[mi][1], al[mi][2], al[mi][3], Al + addr);
            }
            // B frags: pair p covers n-tiles 2p, 2p+1.
            // lane mapping: sub0: n=r koff0, sub1: n=r +16B, sub2: n=r+8 koff0, sub3: n=r+8 +16B
#pragma unroll
            for (int p = 0; p < 2; ++p) {
                const int nrow = wn * 32 + p * 16 + r8 + (sub >> 1) * 8;
                const uint32_t addr = nrow * PITCH + ks * 32 + (sub & 1) * 16;
                uint32_t r0, r1, r2, r3;
                ldm_x4(r0, r1, r2, r3, Bh + addr);
                bh[2 * p][0] = r0; bh[2 * p][1] = r1;
                bh[2 * p + 1][0] = r2; bh[2 * p + 1][1] = r3;
                ldm_x4(r0, r1, r2, r3, Bl + addr);
                bl[2 * p][0] = r0; bl[2 * p][1] = r1;
                bl[2 * p + 1][0] = r2; bl[2 * p + 1][1] = r3;
            }
#pragma unroll
            for (int mi = 0; mi < 4; ++mi)
#pragma unroll
                for (int nj = 0; nj < 4; ++nj) {
                    mma16816(acc[mi][nj], ah[mi], bh[nj]);
                    mma16816(acc[mi][nj], ah[mi], bl[nj]);
                    mma16816(acc[mi][nj], al[mi], bh[nj]);
                }
        }
    };

    // ---- prologue: chunk 0 into stage 0 ----
    {
        uint4 r[8];
        ldg_batch(0, 0, r); sts_batch(0, 0, r);
        ldg_batch(0, 8, r); sts_batch(0, 8, r);
    }

    // ---- main loop ----
    for (int kc = 0; kc < nc; ++kc) {
        const int cur = kc & 1;
        const int nxt = cur ^ 1;
        __syncthreads();                    // stage cur (chunk kc) visible; stage nxt free
        uint4 r[8];
        const bool more = (kc + 1 < nc);
        if (more) ldg_batch(kc + 1, 0, r);  // prefetch A of next chunk
        compute2(cur, 0);
        if (more) { sts_batch(nxt, 0, r); ldg_batch(kc + 1, 8, r); }
        compute2(cur, 2);
        if (more) sts_batch(nxt, 8, r);
    }

    // ---- epilogue: bias + relu + stores (fp32 and/or bf16 hi/lo) ----
    const int g = lane >> 2;
    const int tq = lane & 3;
#pragma unroll
    for (int nj = 0; nj < 4; ++nj) {
        const int col = wn * 32 + nj * 8 + 2 * tq;
        const float2 bb = *(const float2*)(bias + col);
#pragma unroll
        for (int mi = 0; mi < 4; ++mi) {
            const int row0 = block_row + wm * 64 + mi * 16 + g;
            const int row1 = row0 + 8;
            float d0 = fmaxf(acc[mi][nj][0] + bb.x, 0.f);
            float d1 = fmaxf(acc[mi][nj][1] + bb.y, 0.f);
            float d2 = fmaxf(acc[mi][nj][2] + bb.x, 0.f);
            float d3 = fmaxf(acc[mi][nj][3] + bb.y, 0.f);
            if (row0 < N_NODES) {
                if (outf) *(float2*)(outf + (size_t)row0 * 128 + col) = make_float2(d0, d1);
                if (outhi) {
                    uint32_t h, l; split2(d0, d1, h, l);
                    *(uint32_t*)(outhi + (size_t)row0 * 128 + col) = h;
                    *(uint32_t*)(outlo + (size_t)row0 * 128 + col) = l;
                }
            }
            if (row1 < N_NODES) {
                if (outf) *(float2*)(outf + (size_t)row1 * 128 + col) = make_float2(d2, d3);
                if (outhi) {
                    uint32_t h, l; split2(d2, d3, h, l);
                    *(uint32_t*)(outhi + (size_t)row1 * 128 + col) = h;
                    *(uint32_t*)(outlo + (size_t)row1 * 128 + col) = l;
                }
            }
        }
    }
}

// ---------------- head: logits = t @ Wc1 + bc1  (N=32) ---------------------
__global__ void __launch_bounds__(256) head2_kernel(
    const float* __restrict__ t, const float* __restrict__ Wc1,
    const float* __restrict__ bc1, float* __restrict__ out)
{
    __shared__ float Ws[HIDC * N_TRUCK];
    __shared__ float bs[N_TRUCK];
    int tid = threadIdx.x;
#pragma unroll
    for (int r = 0; r < 4; ++r) {
        int idx = tid + r * 256;
        *(float4*)&Ws[idx * 4] = __ldg((const float4*)(Wc1 + idx * 4));
    }
    if (tid < N_TRUCK) bs[tid] = bc1[tid];
    __syncthreads();

    int row = blockIdx.x * 8 + (tid >> 5);
    int col = tid & 31;
    if (row >= N_NODES) return;
    const float* trow = t + (size_t)row * HIDC;
    float acc = bs[col];
#pragma unroll
    for (int k4 = 0; k4 < 32; ++k4) {
        float4 v = __ldg((const float4*)(trow + k4 * 4));
        acc += v.x * Ws[(k4 * 4 + 0) * N_TRUCK + col];
        acc += v.y * Ws[(k4 * 4 + 1) * N_TRUCK + col];
        acc += v.z * Ws[(k4 * 4 + 2) * N_TRUCK + col];
        acc += v.w * Ws[(k4 * 4 + 3) * N_TRUCK + col];
    }
    out[(size_t)row * N_TRUCK + col] = acc;
}

// ---------------- launch ----------------------------------------------------
extern "C" void kernel_launch(void* const* d_in, const int* in_sizes, int n_in,
                              void* d_out, int out_size)
{
    const float* x      = (const float*)d_in[0];
    const int*   ei     = (const int*)d_in[1];
    const float* W_rel0 = (const float*)d_in[2];
    const float* b_rel0 = (const float*)d_in[3];
    const float* W_root0= (const float*)d_in[4];
    const float* W_rel1 = (const float*)d_in[5];
    const float* b_rel1 = (const float*)d_in[6];
    const float* W_root1= (const float*)d_in[7];
    const float* W_rel2 = (const float*)d_in[8];
    const float* b_rel2 = (const float*)d_in[9];
    const float* W_root2= (const float*)d_in[10];
    const float* Wc0    = (const float*)d_in[11];
    const float* bc0    = (const float*)d_in[12];
    const float* Wc1    = (const float*)d_in[13];
    const float* bc1    = (const float*)d_in[14];
    float* out = (float*)d_out;

    const int* srcp = ei;
    const int* dstp = ei + N_EDGES;

    float *F; __nv_bfloat16 *p0h, *p0l, *p1h, *p1l, *agh, *agl, *wtb;
    cudaGetSymbolAddress((void**)&F,   g_F);
    cudaGetSymbolAddress((void**)&p0h, g_p0h);
    cudaGetSymbolAddress((void**)&p0l, g_p0l);
    cudaGetSymbolAddress((void**)&p1h, g_p1h);
    cudaGetSymbolAddress((void**)&p1l, g_p1l);
    cudaGetSymbolAddress((void**)&agh, g_agh);
    cudaGetSymbolAddress((void**)&agl, g_agl);
    cudaGetSymbolAddress((void**)&wtb, g_wtb);

    cudaFuncSetAttribute(gemm_mma, cudaFuncAttributeMaxDynamicSharedMemorySize, GEMM_SMEM);

    const int nbScan = (N_NODES + 1023) / 1024;

    // CSR build (dst-sorted)
    zero_cnt_kernel<<<(N_NODES + 255) / 256, 256>>>();
    hist_kernel<<<(N_EDGES + 255) / 256, 256>>>(dstp);
    scan_phase1<<<nbScan, 1024>>>();
    scan_phase2<<<1, 32>>>(nbScan);
    scan_phase3<<<(N_NODES + 255) / 256, 256>>>();
    fill_kernel<<<(N_EDGES + 255) / 256, 256>>>(srcp, dstp);

    // prep: split x, transpose+split weights
    const int n4 = N_NODES * HIDC / 4;
    split_kernel<<<(n4 + 255) / 256, 256>>>(x, p0h, p0l, n4);
    wprep_kernel<<<(7 * 16384 + 255) / 256, 256>>>(W_rel0, W_root0, W_rel1, W_root1,
                                                   W_rel2, W_root2, Wc0);

    const int aggGrid  = (N_NODES * 32 + 255) / 256;
    const int gemmGrid = (N_NODES + 127) / 128;
    __nv_bfloat16* wt = wtb;   // slot i at wt + i*16384

    // layer 0: agg(x) ; out -> F + pair1
    agg_kernel<<<aggGrid, 256>>>(x, agh, agl);
    gemm_mma<<<gemmGrid, 256, GEMM_SMEM>>>(agh, agl, p0h, p0l,
        wt + 0*16384, wt + 1*16384, wt + 2*16384, wt + 3*16384,
        b_rel0, F, p1h, p1l, 4, 2);
    // layer 1: agg(F) ; out -> F + pair0
    agg_kernel<<<aggGrid, 256>>>(F, agh, agl);
    gemm_mma<<<gemmGrid, 256, GEMM_SMEM>>>(agh, agl, p1h, p1l,
        wt + 4*16384, wt + 5*16384, wt + 6*16384, wt + 7*16384,
        b_rel1, F, p0h, p0l, 4, 2);
    // layer 2: agg(F) ; out -> pair1 only
    agg_kernel<<<aggGrid, 256>>>(F, agh, agl);
    gemm_mma<<<gemmGrid, 256, GEMM_SMEM>>>(agh, agl, p0h, p0l,
        wt + 8*16384, wt + 9*16384, wt + 10*16384, wt + 11*16384,
        b_rel2, nullptr, p1h, p1l, 4, 2);
    // head linear 1: pair1 -> F (fp32), K=128
    gemm_mma<<<gemmGrid, 256, GEMM_SMEM>>>(nullptr, nullptr, p1h, p1l,
        nullptr, nullptr, wt + 12*16384, wt + 13*16384,
        bc0, F, nullptr, nullptr, 2, 0);
    // head linear 2
    head2_kernel<<<(N_NODES + 7) / 8, 256>>>(F, Wc1, bc1, out);
    (void)in_sizes; (void)n_in; (void)out_size;
}